// round 1
// baseline (speedup 1.0000x reference)
#include <cuda_runtime.h>
#include <math.h>

#define Nn 131072
#define Bb 4096
#define Ee 512
#define Hh 8
#define Dd 64
#define EE (Ee*Ee)

// ---------------- scratch (device globals; no allocation allowed) ----------------
__device__ __align__(16) float g_Acat[4*EE];
__device__ __align__(16) float g_Bcat[4*EE];
__device__ __align__(16) float g_Weff[4*EE];          // [Wq_eff; Wk_eff; Wv_eff; Wo_eff]
__device__ __align__(16) float g_beff[3*Ee];          // [bq_eff; bv_eff; bo_eff]
__device__ __align__(16) float g_qq[Bb*Ee];
__device__ __align__(16) float g_qhat[(size_t)Bb*Hh*Ee];
__device__ __align__(16) float g_logits[(size_t)Nn*Hh];
__device__ __align__(16) float g_m[Bb*Hh];
__device__ __align__(16) float g_invZ[Bb*Hh];
__device__ int   g_segstart[Bb+1];
__device__ __align__(16) float g_xw[(size_t)Bb*Hh*Ee];
__device__ __align__(16) float g_pooled[Bb*Ee];
__device__ __align__(16) float g_outbuf[Bb*Ee];

// ---------------- SGEMM: C[M,N] = alpha * A @ op(B) (+ bias), z-batched ----------
// BM=128, BN=64, BK=16, 256 threads, 8x4 per thread. M%128==0, N%64==0, K%16==0.
#define BM 128
#define BN 64
#define BK 16
#define TM 8
#define TN 4

template<bool TRANSB, bool HASBIAS>
__global__ void __launch_bounds__(256)
sgemm(const float* __restrict__ A, const float* __restrict__ B,
      float* __restrict__ C, const float* __restrict__ bias,
      int K, int lda, int ldb, int ldc,
      long zA, long zB, long zC, int zBias, float alpha)
{
    __shared__ float As[BK][BM+4];
    __shared__ float Bs[BK][BN+4];

    int z = blockIdx.z;
    A += (long)z * zA;
    B += (long)z * zB;
    C += (long)z * zC;

    int bm = blockIdx.y * BM;
    int bn = blockIdx.x * BN;
    int tid = threadIdx.x;
    int tx = tid & 15;
    int ty = tid >> 4;

    float acc[TM][TN];
#pragma unroll
    for (int i = 0; i < TM; i++)
#pragma unroll
        for (int j = 0; j < TN; j++) acc[i][j] = 0.f;

    for (int k0 = 0; k0 < K; k0 += BK) {
        // load A tile 128x16 (transposed into As[k][m])
#pragma unroll
        for (int i = 0; i < 2; i++) {
            int p = tid + i * 256;
            int row = p >> 2;
            int kc = (p & 3) << 2;
            float4 v = *(const float4*)&A[(long)(bm + row) * lda + k0 + kc];
            As[kc + 0][row] = v.x;
            As[kc + 1][row] = v.y;
            As[kc + 2][row] = v.z;
            As[kc + 3][row] = v.w;
        }
        // load B tile 16x64 into Bs[k][n]
        if (!TRANSB) {
            int r = tid >> 4;
            int c = (tid & 15) << 2;
            float4 v = *(const float4*)&B[(long)(k0 + r) * ldb + bn + c];
            *(float4*)&Bs[r][c] = v;
        } else {
            int n = tid >> 2;
            int kc = (tid & 3) << 2;
            float4 v = *(const float4*)&B[(long)(bn + n) * ldb + k0 + kc];
            Bs[kc + 0][n] = v.x;
            Bs[kc + 1][n] = v.y;
            Bs[kc + 2][n] = v.z;
            Bs[kc + 3][n] = v.w;
        }
        __syncthreads();

#pragma unroll
        for (int k = 0; k < BK; k++) {
            float4 a0 = *(const float4*)&As[k][ty * TM];
            float4 a1 = *(const float4*)&As[k][ty * TM + 4];
            float4 bv = *(const float4*)&Bs[k][tx * TN];
            float ar[TM] = {a0.x, a0.y, a0.z, a0.w, a1.x, a1.y, a1.z, a1.w};
            float br[TN] = {bv.x, bv.y, bv.z, bv.w};
#pragma unroll
            for (int i = 0; i < TM; i++)
#pragma unroll
                for (int j = 0; j < TN; j++) acc[i][j] += ar[i] * br[j];
        }
        __syncthreads();
    }

    float4 bb = make_float4(0.f, 0.f, 0.f, 0.f);
    if (HASBIAS) {
        const float* bp = bias + (long)z * zBias + bn + tx * TN;
        bb = make_float4(bp[0], bp[1], bp[2], bp[3]);
    }
#pragma unroll
    for (int i = 0; i < TM; i++) {
        int row = bm + ty * TM + i;
        float4 o;
        o.x = alpha * acc[i][0] + bb.x;
        o.y = alpha * acc[i][1] + bb.y;
        o.z = alpha * acc[i][2] + bb.z;
        o.w = alpha * acc[i][3] + bb.w;
        *(float4*)&C[(long)row * ldc + bn + tx * TN] = o;
    }
}

// ---------------- bias folding: bq_eff, bv_eff, bo_eff -----------------
__global__ void bias_fold(const float* __restrict__ ipw, const float* __restrict__ ipb,
                          const float* __restrict__ bq,  const float* __restrict__ bv,
                          const float* __restrict__ out_w, const float* __restrict__ mob,
                          const float* __restrict__ out_b)
{
    int gw = (blockIdx.x * blockDim.x + threadIdx.x) >> 5;
    int lane = threadIdx.x & 31;
    if (gw >= 3 * Ee) return;
    int which = gw / Ee, i = gw % Ee;
    const float* rowp;
    const float* vec;
    float add;
    if (which == 0)      { rowp = ipw + (long)i * Ee;            vec = bq;  add = ipb[i]; }
    else if (which == 1) { rowp = ipw + (long)(2 * Ee + i) * Ee; vec = bv;  add = ipb[2 * Ee + i]; }
    else                 { rowp = out_w + (long)i * Ee;          vec = mob; add = out_b[i]; }
    float s = 0.f;
    for (int k = lane; k < Ee; k += 32) s += rowp[k] * vec[k];
#pragma unroll
    for (int o = 16; o; o >>= 1) s += __shfl_xor_sync(0xffffffffu, s, o);
    if (lane == 0) g_beff[gw] = s + add;
}

// ---------------- segment starts (batch sorted, all B present) -----------------
__global__ void segstart_kernel(const int* __restrict__ batch)
{
    int n = blockIdx.x * 256 + threadIdx.x;
    if (n < Nn) {
        int b = batch[n];
        if (n == 0 || batch[n - 1] != b) g_segstart[b] = n;
    }
    if (n == 0) g_segstart[Bb] = Nn;
}

// ---------------- pass A: logits[n,h] = x_n . qhat[batch[n],h] -----------------
__global__ void __launch_bounds__(256) logits_kernel(const float* __restrict__ X,
                                                     const int* __restrict__ batch)
{
    int warp = (blockIdx.x * 256 + threadIdx.x) >> 5;
    int lane = threadIdx.x & 31;
    if (warp >= Nn) return;
    int n = warp;
    int b = batch[n];

    const float4* xr = (const float4*)(X + (long)n * Ee);
    float4 xv[4];
#pragma unroll
    for (int i = 0; i < 4; i++) xv[i] = xr[lane + 32 * i];

    const float4* qr = (const float4*)(g_qhat + (long)b * Hh * Ee);
    float acc[Hh];
#pragma unroll
    for (int h = 0; h < Hh; h++) {
        float s = 0.f;
#pragma unroll
        for (int i = 0; i < 4; i++) {
            float4 q = qr[h * 128 + lane + 32 * i];
            s += xv[i].x * q.x + xv[i].y * q.y + xv[i].z * q.z + xv[i].w * q.w;
        }
#pragma unroll
        for (int o = 16; o; o >>= 1) s += __shfl_xor_sync(0xffffffffu, s, o);
        acc[h] = s;
    }
    if (lane == 0) {
#pragma unroll
        for (int h = 0; h < Hh; h++) g_logits[(long)n * Hh + h] = acc[h];
    }
}

// ---------------- segment softmax stats: m[b,h], invZ[b,h] -----------------
__global__ void __launch_bounds__(256) stats_kernel()
{
    int warp = (blockIdx.x * 256 + threadIdx.x) >> 5;
    int lane = threadIdx.x & 31;
    if (warp >= Bb) return;
    int b = warp;
    int s0 = g_segstart[b], e0 = g_segstart[b + 1];

    float m[Hh];
#pragma unroll
    for (int h = 0; h < Hh; h++) m[h] = -1e30f;
    for (int n = s0 + lane; n < e0; n += 32) {
        float4 l0 = *(const float4*)&g_logits[(long)n * Hh];
        float4 l1 = *(const float4*)&g_logits[(long)n * Hh + 4];
        float v[8] = {l0.x, l0.y, l0.z, l0.w, l1.x, l1.y, l1.z, l1.w};
#pragma unroll
        for (int h = 0; h < Hh; h++) m[h] = fmaxf(m[h], v[h]);
    }
#pragma unroll
    for (int h = 0; h < Hh; h++)
#pragma unroll
        for (int o = 16; o; o >>= 1) m[h] = fmaxf(m[h], __shfl_xor_sync(0xffffffffu, m[h], o));

    float sum[Hh];
#pragma unroll
    for (int h = 0; h < Hh; h++) sum[h] = 0.f;
    for (int n = s0 + lane; n < e0; n += 32) {
        float4 l0 = *(const float4*)&g_logits[(long)n * Hh];
        float4 l1 = *(const float4*)&g_logits[(long)n * Hh + 4];
        float v[8] = {l0.x, l0.y, l0.z, l0.w, l1.x, l1.y, l1.z, l1.w};
#pragma unroll
        for (int h = 0; h < Hh; h++) sum[h] += __expf(v[h] - m[h]);
    }
#pragma unroll
    for (int h = 0; h < Hh; h++)
#pragma unroll
        for (int o = 16; o; o >>= 1) sum[h] += __shfl_xor_sync(0xffffffffu, sum[h], o);

    if (lane == 0) {
#pragma unroll
        for (int h = 0; h < Hh; h++) {
            g_m[b * Hh + h] = m[h];
            g_invZ[b * Hh + h] = 1.f / sum[h];
        }
    }
}

// ---------------- pass C: xw[b,h,:] = sum_n w[n,h] * x[n,:] -----------------
__global__ void __launch_bounds__(256) xw_kernel(const float* __restrict__ X)
{
    int b = blockIdx.x;
    int t = threadIdx.x;
    int s0 = g_segstart[b], e0 = g_segstart[b + 1];

    __shared__ float wsh[32][8];
    float acc[16];
#pragma unroll
    for (int i = 0; i < 16; i++) acc[i] = 0.f;

    for (int base = s0; base < e0; base += 32) {
        int cnt = min(32, e0 - base);
        if (t < cnt * 8) {
            int i = t >> 3, h = t & 7;
            int n = base + i;
            wsh[i][h] = __expf(g_logits[(long)n * Hh + h] - g_m[b * Hh + h]) * g_invZ[b * Hh + h];
        }
        __syncthreads();
        for (int i = 0; i < cnt; i++) {
            int n = base + i;
            float x0 = X[(long)n * Ee + t];
            float x1 = X[(long)n * Ee + t + 256];
            float4 w0 = *(const float4*)&wsh[i][0];
            float4 w1 = *(const float4*)&wsh[i][4];
            float w[8] = {w0.x, w0.y, w0.z, w0.w, w1.x, w1.y, w1.z, w1.w};
#pragma unroll
            for (int h = 0; h < 8; h++) {
                acc[h * 2 + 0] += w[h] * x0;
                acc[h * 2 + 1] += w[h] * x1;
            }
        }
        __syncthreads();
    }
#pragma unroll
    for (int h = 0; h < 8; h++) {
        g_xw[((long)b * Hh + h) * Ee + t]       = acc[h * 2 + 0];
        g_xw[((long)b * Hh + h) * Ee + t + 256] = acc[h * 2 + 1];
    }
}

// ---------------- LayerNorm over rows of outbuf -> d_out -----------------
__global__ void __launch_bounds__(256) ln_kernel(const float* __restrict__ lng,
                                                 const float* __restrict__ lnb,
                                                 float* __restrict__ out)
{
    int b = blockIdx.x;
    int t = threadIdx.x;
    float v0 = g_outbuf[(long)b * Ee + t];
    float v1 = g_outbuf[(long)b * Ee + t + 256];
    float s = v0 + v1;
    float q = v0 * v0 + v1 * v1;
#pragma unroll
    for (int o = 16; o; o >>= 1) {
        s += __shfl_xor_sync(0xffffffffu, s, o);
        q += __shfl_xor_sync(0xffffffffu, q, o);
    }
    __shared__ float ss[8], qs[8];
    __shared__ float mu_s, r_s;
    int wid = t >> 5, lane = t & 31;
    if (lane == 0) { ss[wid] = s; qs[wid] = q; }
    __syncthreads();
    if (t == 0) {
        float S = 0.f, Q = 0.f;
#pragma unroll
        for (int i = 0; i < 8; i++) { S += ss[i]; Q += qs[i]; }
        float mu = S / (float)Ee;
        float var = Q / (float)Ee - mu * mu;
        mu_s = mu;
        r_s = 1.f / sqrtf(var + 1e-5f);
    }
    __syncthreads();
    float mu = mu_s, r = r_s;
    out[(long)b * Ee + t]       = (v0 - mu) * r * lng[t]       + lnb[t];
    out[(long)b * Ee + t + 256] = (v1 - mu) * r * lng[t + 256] + lnb[t + 256];
}

// ---------------- launch -----------------
extern "C" void kernel_launch(void* const* d_in, const int* in_sizes, int n_in,
                              void* d_out, int out_size)
{
    (void)in_sizes; (void)n_in; (void)out_size;
    const float* X        = (const float*)d_in[0];   // node_features [N,E]
    const float* scaffold = (const float*)d_in[1];   // [B,E]
    const float* Wq       = (const float*)d_in[2];
    const float* bq       = (const float*)d_in[3];
    const float* Wk       = (const float*)d_in[4];
    const float* Wv       = (const float*)d_in[6];
    const float* bv       = (const float*)d_in[7];
    const float* ipw      = (const float*)d_in[8];   // in_proj_w [3E,E]
    const float* ipb      = (const float*)d_in[9];
    const float* mow      = (const float*)d_in[10];  // mha_out_w
    const float* mob      = (const float*)d_in[11];
    const float* ow       = (const float*)d_in[12];  // out_w
    const float* ob       = (const float*)d_in[13];
    const float* lng      = (const float*)d_in[14];
    const float* lnb      = (const float*)d_in[15];
    const int*   batch    = (const int*)d_in[16];

    void* p;
    cudaGetSymbolAddress(&p, g_Acat);   float* Acat   = (float*)p;
    cudaGetSymbolAddress(&p, g_Bcat);   float* Bcat   = (float*)p;
    cudaGetSymbolAddress(&p, g_Weff);   float* Weff   = (float*)p;
    cudaGetSymbolAddress(&p, g_beff);   float* beff   = (float*)p;
    cudaGetSymbolAddress(&p, g_qq);     float* qq     = (float*)p;
    cudaGetSymbolAddress(&p, g_qhat);   float* qhat   = (float*)p;
    cudaGetSymbolAddress(&p, g_xw);     float* xw     = (float*)p;
    cudaGetSymbolAddress(&p, g_pooled); float* pooled = (float*)p;
    cudaGetSymbolAddress(&p, g_outbuf); float* outbuf = (float*)p;

    // concat fold operands: Acat=[Wiq;Wik;Wiv;out_w], Bcat=[Wq;Wk;Wv;mha_out_w]
    cudaMemcpyAsync(Acat,          ipw, (size_t)3 * EE * sizeof(float), cudaMemcpyDeviceToDevice, 0);
    cudaMemcpyAsync(Acat + 3 * EE, ow,  (size_t)EE * sizeof(float),     cudaMemcpyDeviceToDevice, 0);
    cudaMemcpyAsync(Bcat,          Wq,  (size_t)EE * sizeof(float),     cudaMemcpyDeviceToDevice, 0);
    cudaMemcpyAsync(Bcat + EE,     Wk,  (size_t)EE * sizeof(float),     cudaMemcpyDeviceToDevice, 0);
    cudaMemcpyAsync(Bcat + 2 * EE, Wv,  (size_t)EE * sizeof(float),     cudaMemcpyDeviceToDevice, 0);
    cudaMemcpyAsync(Bcat + 3 * EE, mow, (size_t)EE * sizeof(float),     cudaMemcpyDeviceToDevice, 0);

    // fold: Weff[z] = Acat[z] @ Bcat[z]  (z = q,k,v,o), 512x512x512 each
    sgemm<false, false><<<dim3(8, 4, 4), 256>>>(Acat, Bcat, Weff, nullptr,
        512, 512, 512, 512, (long)EE, (long)EE, (long)EE, 0, 1.f);

    bias_fold<<<192, 256>>>(ipw, ipb, bq, bv, ow, mob, ob);

    // qq = scaffold @ Wq_eff^T + bq_eff   [4096,512,512] NT
    sgemm<true, true><<<dim3(8, 32, 1), 256>>>(scaffold, Weff, qq, beff,
        512, Ee, Ee, Ee, 0, 0, 0, 0, 1.f);

    // qhat[b,h,:] = scale * qq[b,h,:] @ Wk_eff_h    [4096,512,64] NN x 8 heads
    sgemm<false, false><<<dim3(8, 32, 8), 256>>>(qq, Weff + EE, qhat, nullptr,
        Dd, Ee, Ee, Hh * Ee, (long)Dd, (long)Dd * Ee, (long)Ee, 0, 0.125f);

    segstart_kernel<<<Nn / 256, 256>>>(batch);
    logits_kernel<<<Nn / 8, 256>>>(X, batch);
    stats_kernel<<<Bb / 8, 256>>>();
    xw_kernel<<<Bb, 256>>>(X);

    // pooled[b, h*D+:] = xw[b,h,:] @ Wv_eff_h^T + bv_eff   [4096,64,512] NT x 8 heads
    sgemm<true, true><<<dim3(1, 32, 8), 256>>>(xw, Weff + 2 * EE, pooled, beff + Ee,
        512, Hh * Ee, Ee, Ee, (long)Ee, (long)Dd * Ee, (long)Dd, Dd, 1.f);

    // out = pooled @ Wo_eff^T + bo_eff   [4096,512,512] NT
    sgemm<true, true><<<dim3(8, 32, 1), 256>>>(pooled, Weff + 3 * EE, outbuf, beff + 2 * Ee,
        512, Ee, Ee, Ee, 0, 0, 0, 0, 1.f);

    ln_kernel<<<Bb, 256>>>(lng, lnb, (float*)d_out);
}

// round 3
// speedup vs baseline: 1.4528x; 1.4528x over previous
#include <cuda_runtime.h>
#include <cuda_bf16.h>
#include <math.h>
#include <stdint.h>

#define Nn 131072
#define Bb 4096
#define Ee 512
#define Hh 8
#define Dd 64
#define EE (Ee*Ee)

// ---------------- scratch (device globals; no allocation allowed) ----------------
__device__ __align__(16) float g_Acat[4*EE];
__device__ __align__(16) float g_Bcat[4*EE];
__device__ __align__(16) float g_Weff[4*EE];          // [Wq_eff; Wk_eff; Wv_eff; Wo_eff]
__device__ __align__(16) float g_beff[3*Ee];          // [bq_eff; bv_eff; bo_eff]
__device__ __align__(16) float g_qq[Bb*Ee];
__device__ __align__(16) float g_qhat[(size_t)Bb*Hh*Ee];
__device__ __align__(16) float g_logits[(size_t)Nn*Hh];
__device__ __align__(16) float g_m[Bb*Hh];
__device__ __align__(16) float g_invZ[Bb*Hh];
__device__ int   g_segstart[Bb+1];
__device__ __align__(16) float g_xw[(size_t)Bb*Hh*Ee];
__device__ __align__(16) float g_pooled[Bb*Ee];
__device__ __align__(16) float g_outbuf[Bb*Ee];

// ================= mma.sync helpers (compute_103 baseline features) =============
__device__ __forceinline__ uint32_t smem_u32(const void* p) {
    uint32_t a;
    asm("{ .reg .u64 t; cvta.to.shared.u64 t, %1; cvt.u32.u64 %0, t; }" : "=r"(a) : "l"(p));
    return a;
}

__device__ __forceinline__ void ldsm4(uint32_t* r, uint32_t addr) {
    asm volatile("ldmatrix.sync.aligned.m8n8.x4.shared.b16 {%0,%1,%2,%3}, [%4];"
        : "=r"(r[0]), "=r"(r[1]), "=r"(r[2]), "=r"(r[3]) : "r"(addr));
}
__device__ __forceinline__ void ldsm4t(uint32_t* r, uint32_t addr) {
    asm volatile("ldmatrix.sync.aligned.m8n8.x4.trans.shared.b16 {%0,%1,%2,%3}, [%4];"
        : "=r"(r[0]), "=r"(r[1]), "=r"(r[2]), "=r"(r[3]) : "r"(addr));
}
__device__ __forceinline__ void mma16816(float* c, const uint32_t* a, const uint32_t* b) {
    asm volatile("mma.sync.aligned.m16n8k16.row.col.f32.bf16.bf16.f32 "
        "{%0,%1,%2,%3}, {%4,%5,%6,%7}, {%8,%9}, {%0,%1,%2,%3};"
        : "+f"(c[0]), "+f"(c[1]), "+f"(c[2]), "+f"(c[3])
        : "r"(a[0]), "r"(a[1]), "r"(a[2]), "r"(a[3]), "r"(b[0]), "r"(b[1]));
}

// ---------- fp32 -> bf16 hi/lo split ----------
__device__ __forceinline__ void split4(float4 v, uint2& hi, uint2& lo) {
    __nv_bfloat162 h0 = __floats2bfloat162_rn(v.x, v.y);
    __nv_bfloat162 h1 = __floats2bfloat162_rn(v.z, v.w);
    float2 f0 = __bfloat1622float2(h0);
    float2 f1 = __bfloat1622float2(h1);
    __nv_bfloat162 l0 = __floats2bfloat162_rn(v.x - f0.x, v.y - f0.y);
    __nv_bfloat162 l1 = __floats2bfloat162_rn(v.z - f1.x, v.w - f1.y);
    hi.x = *(uint32_t*)&h0; hi.y = *(uint32_t*)&h1;
    lo.x = *(uint32_t*)&l0; lo.y = *(uint32_t*)&l1;
}

// ================= HMMA GEMM =================
// C[M,N] = alpha * A @ op(B) (+ bias), z-batched. BM=128, BN=64, K chunk=64.
// fp32 emulated as bf16 hi/lo: hi*hi + hi*lo + lo*hi.  M%128==0, N%64==0, K%64==0.
// Padded SMEM rows: 72 bf16 = 144B stride (8 ldmatrix segments hit 8 distinct
// 16B groups mod 128 -> conflict-free).
#define ROWB 144
#define SM_AHI 0
#define SM_ALO 18432
#define SM_BHI 36864
#define SM_BLO 46080
#define SM_TOTAL 55296

template<bool TRANSB, bool HASBIAS>
__global__ void __launch_bounds__(256, 2)
tcgemm(const float* __restrict__ A, const float* __restrict__ B,
       float* __restrict__ C, const float* __restrict__ bias,
       int K, int lda, int ldb, int ldc,
       long zA, long zB, long zC, int zBias, float alpha)
{
    extern __shared__ __align__(16) char sm[];
    uint32_t sb = smem_u32(sm);

    int z = blockIdx.z;
    A += (long)z * zA;
    B += (long)z * zB;
    C += (long)z * zC;
    int bm = blockIdx.y * 128;
    int bn = blockIdx.x * 64;
    int tid = threadIdx.x;
    int wid = tid >> 5;
    int lane = tid & 31;
    int wm = wid & 3;      // 4 warps along m (32 rows each)
    int wn = wid >> 2;     // 2 warps along n (32 cols each)

    float acc[2][4][4];
#pragma unroll
    for (int i = 0; i < 2; i++)
#pragma unroll
        for (int f = 0; f < 4; f++)
#pragma unroll
            for (int r = 0; r < 4; r++) acc[i][f][r] = 0.f;

    // ldmatrix per-thread address components
    int am = ((lane >> 3) & 1) * 8 + (lane & 7);   // row within m16 tile pair
    int ak = (lane >> 4) * 8;                      // k8 select
    // B (TRANSB: SMEM rows = n, non-trans ldsm)
    int bnr = ((lane >> 4) & 1) * 8 + (lane & 7);
    int bkc = ((lane >> 3) & 1) * 8;
    // B (!TRANSB: SMEM rows = k, trans ldsm)
    int bkr = ((lane >> 3) & 1) * 8 + (lane & 7);
    int bnc = (lane >> 4) * 8;

    const int nch = K / 64;
    for (int ch = 0; ch < nch; ch++) {
        int k0 = ch * 64;

        // ---- A chunk: [128 x 64] fp32 -> bf16 hi/lo ----
#pragma unroll
        for (int i = 0; i < 8; i++) {
            int p = tid + i * 256;
            int row = p >> 4;
            int c4 = p & 15;
            float4 v = *(const float4*)&A[(long)(bm + row) * lda + k0 + c4 * 4];
            uint2 hi, lo;
            split4(v, hi, lo);
            uint32_t off = row * ROWB + c4 * 8;
            *(uint2*)(sm + SM_AHI + off) = hi;
            *(uint2*)(sm + SM_ALO + off) = lo;
        }
        // ---- B chunk: 64x64 ----
#pragma unroll
        for (int i = 0; i < 4; i++) {
            int p = tid + i * 256;
            int row = p >> 4;
            int c4 = p & 15;
            const float* src = TRANSB ? &B[(long)(bn + row) * ldb + k0 + c4 * 4]
                                      : &B[(long)(k0 + row) * ldb + bn + c4 * 4];
            float4 v = *(const float4*)src;
            uint2 hi, lo;
            split4(v, hi, lo);
            uint32_t off = row * ROWB + c4 * 8;
            *(uint2*)(sm + SM_BHI + off) = hi;
            *(uint2*)(sm + SM_BLO + off) = lo;
        }
        __syncthreads();

#pragma unroll
        for (int ks = 0; ks < 4; ks++) {
            int kk = ks * 16;
            // B fragments: 4 n8-frags x {b0,b1}, hi and lo
            uint32_t bh[4][2], bl[4][2];
#pragma unroll
            for (int g = 0; g < 2; g++) {
                uint32_t r[4];
                if (TRANSB) {
                    uint32_t off = (uint32_t)(wn * 32 + g * 16 + bnr) * ROWB + (kk + bkc) * 2;
                    ldsm4(r, sb + SM_BHI + off);
                    bh[g*2][0]=r[0]; bh[g*2][1]=r[1]; bh[g*2+1][0]=r[2]; bh[g*2+1][1]=r[3];
                    ldsm4(r, sb + SM_BLO + off);
                    bl[g*2][0]=r[0]; bl[g*2][1]=r[1]; bl[g*2+1][0]=r[2]; bl[g*2+1][1]=r[3];
                } else {
                    uint32_t off = (uint32_t)(kk + bkr) * ROWB + (wn * 32 + g * 16 + bnc) * 2;
                    ldsm4t(r, sb + SM_BHI + off);
                    bh[g*2][0]=r[0]; bh[g*2][1]=r[1]; bh[g*2+1][0]=r[2]; bh[g*2+1][1]=r[3];
                    ldsm4t(r, sb + SM_BLO + off);
                    bl[g*2][0]=r[0]; bl[g*2][1]=r[1]; bl[g*2+1][0]=r[2]; bl[g*2+1][1]=r[3];
                }
            }
            // A fragments: 2 m16-frags, hi and lo
            uint32_t ah[2][4], al[2][4];
#pragma unroll
            for (int i = 0; i < 2; i++) {
                uint32_t off = (uint32_t)(wm * 32 + i * 16 + am) * ROWB + (kk + ak) * 2;
                ldsm4(ah[i], sb + SM_AHI + off);
                ldsm4(al[i], sb + SM_ALO + off);
            }
#pragma unroll
            for (int i = 0; i < 2; i++)
#pragma unroll
                for (int f = 0; f < 4; f++) {
                    mma16816(acc[i][f], ah[i], bh[f]);
                    mma16816(acc[i][f], ah[i], bl[f]);
                    mma16816(acc[i][f], al[i], bh[f]);
                }
        }
        __syncthreads();
    }

    // ---- epilogue ----
#pragma unroll
    for (int i = 0; i < 2; i++) {
#pragma unroll
        for (int f = 0; f < 4; f++) {
            int row = bm + wm * 32 + i * 16 + (lane >> 2);
            int col = bn + wn * 32 + f * 8 + (lane & 3) * 2;
            float2 bb = make_float2(0.f, 0.f);
            if (HASBIAS) bb = *(const float2*)&bias[(long)z * zBias + col - bn + bn];  // bias indexed by col
            float2 o0, o1;
            o0.x = alpha * acc[i][f][0] + bb.x;
            o0.y = alpha * acc[i][f][1] + bb.y;
            o1.x = alpha * acc[i][f][2] + bb.x;
            o1.y = alpha * acc[i][f][3] + bb.y;
            *(float2*)&C[(long)row * ldc + col] = o0;
            *(float2*)&C[(long)(row + 8) * ldc + col] = o1;
        }
    }
}

// ---------------- bias folding: bq_eff, bv_eff, bo_eff -----------------
__global__ void bias_fold(const float* __restrict__ ipw, const float* __restrict__ ipb,
                          const float* __restrict__ bq,  const float* __restrict__ bv,
                          const float* __restrict__ out_w, const float* __restrict__ mob,
                          const float* __restrict__ out_b)
{
    int gw = (blockIdx.x * blockDim.x + threadIdx.x) >> 5;
    int lane = threadIdx.x & 31;
    if (gw >= 3 * Ee) return;
    int which = gw / Ee, i = gw % Ee;
    const float* rowp;
    const float* vec;
    float add;
    if (which == 0)      { rowp = ipw + (long)i * Ee;            vec = bq;  add = ipb[i]; }
    else if (which == 1) { rowp = ipw + (long)(2 * Ee + i) * Ee; vec = bv;  add = ipb[2 * Ee + i]; }
    else                 { rowp = out_w + (long)i * Ee;          vec = mob; add = out_b[i]; }
    float s = 0.f;
    for (int k = lane; k < Ee; k += 32) s += rowp[k] * vec[k];
#pragma unroll
    for (int o = 16; o; o >>= 1) s += __shfl_xor_sync(0xffffffffu, s, o);
    if (lane == 0) g_beff[gw] = s + add;
}

// ---------------- segment starts (batch sorted, all B present) -----------------
__global__ void segstart_kernel(const int* __restrict__ batch)
{
    int n = blockIdx.x * 256 + threadIdx.x;
    if (n < Nn) {
        int b = batch[n];
        if (n == 0 || batch[n - 1] != b) g_segstart[b] = n;
    }
    if (n == 0) g_segstart[Bb] = Nn;
}

// ---------------- pass A: logits[n,h] = x_n . qhat[batch[n],h] -----------------
__global__ void __launch_bounds__(256) logits_kernel(const float* __restrict__ X,
                                                     const int* __restrict__ batch)
{
    int warp = (blockIdx.x * 256 + threadIdx.x) >> 5;
    int lane = threadIdx.x & 31;
    if (warp >= Nn) return;
    int n = warp;
    int b = batch[n];

    const float4* xr = (const float4*)(X + (long)n * Ee);
    float4 xv[4];
#pragma unroll
    for (int i = 0; i < 4; i++) xv[i] = xr[lane + 32 * i];

    const float4* qr = (const float4*)(g_qhat + (long)b * Hh * Ee);
    float acc[Hh];
#pragma unroll
    for (int h = 0; h < Hh; h++) {
        float s = 0.f;
#pragma unroll
        for (int i = 0; i < 4; i++) {
            float4 q = qr[h * 128 + lane + 32 * i];
            s += xv[i].x * q.x + xv[i].y * q.y + xv[i].z * q.z + xv[i].w * q.w;
        }
#pragma unroll
        for (int o = 16; o; o >>= 1) s += __shfl_xor_sync(0xffffffffu, s, o);
        acc[h] = s;
    }
    if (lane == 0) {
#pragma unroll
        for (int h = 0; h < Hh; h++) g_logits[(long)n * Hh + h] = acc[h];
    }
}

// ---------------- segment softmax stats: m[b,h], invZ[b,h] -----------------
__global__ void __launch_bounds__(256) stats_kernel()
{
    int warp = (blockIdx.x * 256 + threadIdx.x) >> 5;
    int lane = threadIdx.x & 31;
    if (warp >= Bb) return;
    int b = warp;
    int s0 = g_segstart[b], e0 = g_segstart[b + 1];

    float m[Hh];
#pragma unroll
    for (int h = 0; h < Hh; h++) m[h] = -1e30f;
    for (int n = s0 + lane; n < e0; n += 32) {
        float4 l0 = *(const float4*)&g_logits[(long)n * Hh];
        float4 l1 = *(const float4*)&g_logits[(long)n * Hh + 4];
        float v[8] = {l0.x, l0.y, l0.z, l0.w, l1.x, l1.y, l1.z, l1.w};
#pragma unroll
        for (int h = 0; h < Hh; h++) m[h] = fmaxf(m[h], v[h]);
    }
#pragma unroll
    for (int h = 0; h < Hh; h++)
#pragma unroll
        for (int o = 16; o; o >>= 1) m[h] = fmaxf(m[h], __shfl_xor_sync(0xffffffffu, m[h], o));

    float sum[Hh];
#pragma unroll
    for (int h = 0; h < Hh; h++) sum[h] = 0.f;
    for (int n = s0 + lane; n < e0; n += 32) {
        float4 l0 = *(const float4*)&g_logits[(long)n * Hh];
        float4 l1 = *(const float4*)&g_logits[(long)n * Hh + 4];
        float v[8] = {l0.x, l0.y, l0.z, l0.w, l1.x, l1.y, l1.z, l1.w};
#pragma unroll
        for (int h = 0; h < Hh; h++) sum[h] += __expf(v[h] - m[h]);
    }
#pragma unroll
    for (int h = 0; h < Hh; h++)
#pragma unroll
        for (int o = 16; o; o >>= 1) sum[h] += __shfl_xor_sync(0xffffffffu, sum[h], o);

    if (lane == 0) {
#pragma unroll
        for (int h = 0; h < Hh; h++) {
            g_m[b * Hh + h] = m[h];
            g_invZ[b * Hh + h] = 1.f / sum[h];
        }
    }
}

// ---------------- pass C: xw[b,h,:] = sum_n w[n,h] * x[n,:] -----------------
__global__ void __launch_bounds__(256) xw_kernel(const float* __restrict__ X)
{
    int b = blockIdx.x;
    int t = threadIdx.x;
    int s0 = g_segstart[b], e0 = g_segstart[b + 1];

    __shared__ float wsh[32][8];
    float acc[16];
#pragma unroll
    for (int i = 0; i < 16; i++) acc[i] = 0.f;

    for (int base = s0; base < e0; base += 32) {
        int cnt = min(32, e0 - base);
        if (t < cnt * 8) {
            int i = t >> 3, h = t & 7;
            int n = base + i;
            wsh[i][h] = __expf(g_logits[(long)n * Hh + h] - g_m[b * Hh + h]) * g_invZ[b * Hh + h];
        }
        __syncthreads();
        for (int i = 0; i < cnt; i++) {
            int n = base + i;
            float x0 = X[(long)n * Ee + t];
            float x1 = X[(long)n * Ee + t + 256];
            float4 w0 = *(const float4*)&wsh[i][0];
            float4 w1 = *(const float4*)&wsh[i][4];
            float w[8] = {w0.x, w0.y, w0.z, w0.w, w1.x, w1.y, w1.z, w1.w};
#pragma unroll
            for (int h = 0; h < 8; h++) {
                acc[h * 2 + 0] += w[h] * x0;
                acc[h * 2 + 1] += w[h] * x1;
            }
        }
        __syncthreads();
    }
#pragma unroll
    for (int h = 0; h < 8; h++) {
        g_xw[((long)b * Hh + h) * Ee + t]       = acc[h * 2 + 0];
        g_xw[((long)b * Hh + h) * Ee + t + 256] = acc[h * 2 + 1];
    }
}

// ---------------- LayerNorm over rows of outbuf -> d_out -----------------
__global__ void __launch_bounds__(256) ln_kernel(const float* __restrict__ lng,
                                                 const float* __restrict__ lnb,
                                                 float* __restrict__ out)
{
    int b = blockIdx.x;
    int t = threadIdx.x;
    float v0 = g_outbuf[(long)b * Ee + t];
    float v1 = g_outbuf[(long)b * Ee + t + 256];
    float s = v0 + v1;
    float q = v0 * v0 + v1 * v1;
#pragma unroll
    for (int o = 16; o; o >>= 1) {
        s += __shfl_xor_sync(0xffffffffu, s, o);
        q += __shfl_xor_sync(0xffffffffu, q, o);
    }
    __shared__ float ss[8], qs[8];
    __shared__ float mu_s, r_s;
    int wid = t >> 5, lane = t & 31;
    if (lane == 0) { ss[wid] = s; qs[wid] = q; }
    __syncthreads();
    if (t == 0) {
        float S = 0.f, Q = 0.f;
#pragma unroll
        for (int i = 0; i < 8; i++) { S += ss[i]; Q += qs[i]; }
        float mu = S / (float)Ee;
        float var = Q / (float)Ee - mu * mu;
        mu_s = mu;
        r_s = 1.f / sqrtf(var + 1e-5f);
    }
    __syncthreads();
    float mu = mu_s, r = r_s;
    out[(long)b * Ee + t]       = (v0 - mu) * r * lng[t]       + lnb[t];
    out[(long)b * Ee + t + 256] = (v1 - mu) * r * lng[t + 256] + lnb[t + 256];
}

// ---------------- launch -----------------
extern "C" void kernel_launch(void* const* d_in, const int* in_sizes, int n_in,
                              void* d_out, int out_size)
{
    (void)in_sizes; (void)n_in; (void)out_size;
    const float* X        = (const float*)d_in[0];   // node_features [N,E]
    const float* scaffold = (const float*)d_in[1];   // [B,E]
    const float* Wq       = (const float*)d_in[2];
    const float* bq       = (const float*)d_in[3];
    const float* Wk       = (const float*)d_in[4];
    const float* Wv       = (const float*)d_in[6];
    const float* bv       = (const float*)d_in[7];
    const float* ipw      = (const float*)d_in[8];   // in_proj_w [3E,E]
    const float* ipb      = (const float*)d_in[9];
    const float* mow      = (const float*)d_in[10];  // mha_out_w
    const float* mob      = (const float*)d_in[11];
    const float* ow       = (const float*)d_in[12];  // out_w
    const float* ob       = (const float*)d_in[13];
    const float* lng      = (const float*)d_in[14];
    const float* lnb      = (const float*)d_in[15];
    const int*   batch    = (const int*)d_in[16];

    void* p;
    cudaGetSymbolAddress(&p, g_Acat);   float* Acat   = (float*)p;
    cudaGetSymbolAddress(&p, g_Bcat);   float* Bcat   = (float*)p;
    cudaGetSymbolAddress(&p, g_Weff);   float* Weff   = (float*)p;
    cudaGetSymbolAddress(&p, g_beff);   float* beff   = (float*)p;
    cudaGetSymbolAddress(&p, g_qq);     float* qq     = (float*)p;
    cudaGetSymbolAddress(&p, g_qhat);   float* qhat   = (float*)p;
    cudaGetSymbolAddress(&p, g_xw);     float* xw     = (float*)p;
    cudaGetSymbolAddress(&p, g_pooled); float* pooled = (float*)p;
    cudaGetSymbolAddress(&p, g_outbuf); float* outbuf = (float*)p;

    cudaFuncSetAttribute(tcgemm<false, false>,
                         cudaFuncAttributeMaxDynamicSharedMemorySize, SM_TOTAL);
    cudaFuncSetAttribute(tcgemm<true, true>,
                         cudaFuncAttributeMaxDynamicSharedMemorySize, SM_TOTAL);

    // concat fold operands: Acat=[Wiq;Wik;Wiv;out_w], Bcat=[Wq;Wk;Wv;mha_out_w]
    cudaMemcpyAsync(Acat,          ipw, (size_t)3 * EE * sizeof(float), cudaMemcpyDeviceToDevice, 0);
    cudaMemcpyAsync(Acat + 3 * EE, ow,  (size_t)EE * sizeof(float),     cudaMemcpyDeviceToDevice, 0);
    cudaMemcpyAsync(Bcat,          Wq,  (size_t)EE * sizeof(float),     cudaMemcpyDeviceToDevice, 0);
    cudaMemcpyAsync(Bcat + EE,     Wk,  (size_t)EE * sizeof(float),     cudaMemcpyDeviceToDevice, 0);
    cudaMemcpyAsync(Bcat + 2 * EE, Wv,  (size_t)EE * sizeof(float),     cudaMemcpyDeviceToDevice, 0);
    cudaMemcpyAsync(Bcat + 3 * EE, mow, (size_t)EE * sizeof(float),     cudaMemcpyDeviceToDevice, 0);

    // fold: Weff[z] = Acat[z] @ Bcat[z]  (z = q,k,v,o), 512x512x512 each (NN)
    tcgemm<false, false><<<dim3(8, 4, 4), 256, SM_TOTAL>>>(Acat, Bcat, Weff, nullptr,
        512, 512, 512, 512, (long)EE, (long)EE, (long)EE, 0, 1.f);

    bias_fold<<<192, 256>>>(ipw, ipb, bq, bv, ow, mob, ob);

    // qq = scaffold @ Wq_eff^T + bq_eff   [4096,512,512] NT
    tcgemm<true, true><<<dim3(8, 32, 1), 256, SM_TOTAL>>>(scaffold, Weff, qq, beff,
        512, Ee, Ee, Ee, 0, 0, 0, 0, 1.f);

    // qhat[b,h,:] = scale * qq[b,h,:] @ Wk_eff_h    [4096,512,64] NN x 8 heads
    tcgemm<false, false><<<dim3(8, 32, 8), 256, SM_TOTAL>>>(qq, Weff + EE, qhat, nullptr,
        Dd, Ee, Ee, Hh * Ee, (long)Dd, (long)Dd * Ee, (long)Ee, 0, 0.125f);

    segstart_kernel<<<Nn / 256, 256>>>(batch);
    logits_kernel<<<Nn / 8, 256>>>(X, batch);
    stats_kernel<<<Bb / 8, 256>>>();
    xw_kernel<<<Bb, 256>>>(X);

    // pooled[b, h*D+:] = xw[b,h,:] @ Wv_eff_h^T + bv_eff   [4096,64,512] NT x 8 heads
    tcgemm<true, true><<<dim3(1, 32, 8), 256, SM_TOTAL>>>(xw, Weff + 2 * EE, pooled, beff + Ee,
        512, Hh * Ee, Ee, Ee, (long)Ee, (long)Dd * Ee, (long)Dd, Dd, 1.f);

    // out = pooled @ Wo_eff^T + bo_eff   [4096,512,512] NT
    tcgemm<true, true><<<dim3(8, 32, 1), 256, SM_TOTAL>>>(pooled, Weff + 3 * EE, outbuf, beff + 2 * Ee,
        512, Ee, Ee, Ee, 0, 0, 0, 0, 1.f);

    ln_kernel<<<Bb, 256>>>(lng, lnb, (float*)d_out);
}

// round 4
// speedup vs baseline: 1.6512x; 1.1366x over previous
#include <cuda_runtime.h>
#include <cuda_bf16.h>
#include <math.h>
#include <stdint.h>

#define Nn 131072
#define Bb 4096
#define Ee 512
#define Hh 8
#define Dd 64
#define EE (Ee*Ee)

// ---------------- scratch (device globals; no allocation allowed) ----------------
__device__ __align__(16) float g_Acat[4*EE];
__device__ __align__(16) float g_Bcat[4*EE];
__device__ __align__(16) float g_Weff[4*EE];          // [Wq_eff; Wk_eff; Wv_eff; Wo_eff]
__device__ __align__(16) float g_beff[3*Ee];          // [bq_eff; bv_eff; bo_eff]
__device__ __align__(16) float g_qq[Bb*Ee];
__device__ __align__(16) float g_qhat[(size_t)Bb*Hh*Ee];
__device__ int   g_segstart[Bb+1];
__device__ __align__(16) float g_xw[(size_t)Bb*Hh*Ee];
__device__ __align__(16) float g_pooled[Bb*Ee];
__device__ __align__(16) float g_outbuf[Bb*Ee];

// ================= mma.sync helpers (compute_103 baseline features) =============
__device__ __forceinline__ uint32_t smem_u32(const void* p) {
    uint32_t a;
    asm("{ .reg .u64 t; cvta.to.shared.u64 t, %1; cvt.u32.u64 %0, t; }" : "=r"(a) : "l"(p));
    return a;
}

__device__ __forceinline__ void ldsm4(uint32_t* r, uint32_t addr) {
    asm volatile("ldmatrix.sync.aligned.m8n8.x4.shared.b16 {%0,%1,%2,%3}, [%4];"
        : "=r"(r[0]), "=r"(r[1]), "=r"(r[2]), "=r"(r[3]) : "r"(addr));
}
__device__ __forceinline__ void ldsm4t(uint32_t* r, uint32_t addr) {
    asm volatile("ldmatrix.sync.aligned.m8n8.x4.trans.shared.b16 {%0,%1,%2,%3}, [%4];"
        : "=r"(r[0]), "=r"(r[1]), "=r"(r[2]), "=r"(r[3]) : "r"(addr));
}
__device__ __forceinline__ void mma16816(float* c, const uint32_t* a, const uint32_t* b) {
    asm volatile("mma.sync.aligned.m16n8k16.row.col.f32.bf16.bf16.f32 "
        "{%0,%1,%2,%3}, {%4,%5,%6,%7}, {%8,%9}, {%0,%1,%2,%3};"
        : "+f"(c[0]), "+f"(c[1]), "+f"(c[2]), "+f"(c[3])
        : "r"(a[0]), "r"(a[1]), "r"(a[2]), "r"(a[3]), "r"(b[0]), "r"(b[1]));
}

// ---------- fp32 -> bf16 hi/lo split ----------
__device__ __forceinline__ void split4(float4 v, uint2& hi, uint2& lo) {
    __nv_bfloat162 h0 = __floats2bfloat162_rn(v.x, v.y);
    __nv_bfloat162 h1 = __floats2bfloat162_rn(v.z, v.w);
    float2 f0 = __bfloat1622float2(h0);
    float2 f1 = __bfloat1622float2(h1);
    __nv_bfloat162 l0 = __floats2bfloat162_rn(v.x - f0.x, v.y - f0.y);
    __nv_bfloat162 l1 = __floats2bfloat162_rn(v.z - f1.x, v.w - f1.y);
    hi.x = *(uint32_t*)&h0; hi.y = *(uint32_t*)&h1;
    lo.x = *(uint32_t*)&l0; lo.y = *(uint32_t*)&l1;
}

// ================= HMMA GEMM (unchanged from R3, passing) =================
#define ROWB 144
#define SM_AHI 0
#define SM_ALO 18432
#define SM_BHI 36864
#define SM_BLO 46080
#define SM_TOTAL 55296

template<bool TRANSB, bool HASBIAS>
__global__ void __launch_bounds__(256, 2)
tcgemm(const float* __restrict__ A, const float* __restrict__ B,
       float* __restrict__ C, const float* __restrict__ bias,
       int K, int lda, int ldb, int ldc,
       long zA, long zB, long zC, int zBias, float alpha)
{
    extern __shared__ __align__(16) char sm[];
    uint32_t sb = smem_u32(sm);

    int z = blockIdx.z;
    A += (long)z * zA;
    B += (long)z * zB;
    C += (long)z * zC;
    int bm = blockIdx.y * 128;
    int bn = blockIdx.x * 64;
    int tid = threadIdx.x;
    int wid = tid >> 5;
    int lane = tid & 31;
    int wm = wid & 3;
    int wn = wid >> 2;

    float acc[2][4][4];
#pragma unroll
    for (int i = 0; i < 2; i++)
#pragma unroll
        for (int f = 0; f < 4; f++)
#pragma unroll
            for (int r = 0; r < 4; r++) acc[i][f][r] = 0.f;

    int am = ((lane >> 3) & 1) * 8 + (lane & 7);
    int ak = (lane >> 4) * 8;
    int bnr = ((lane >> 4) & 1) * 8 + (lane & 7);
    int bkc = ((lane >> 3) & 1) * 8;
    int bkr = ((lane >> 3) & 1) * 8 + (lane & 7);
    int bnc = (lane >> 4) * 8;

    const int nch = K / 64;
    for (int ch = 0; ch < nch; ch++) {
        int k0 = ch * 64;

#pragma unroll
        for (int i = 0; i < 8; i++) {
            int p = tid + i * 256;
            int row = p >> 4;
            int c4 = p & 15;
            float4 v = *(const float4*)&A[(long)(bm + row) * lda + k0 + c4 * 4];
            uint2 hi, lo;
            split4(v, hi, lo);
            uint32_t off = row * ROWB + c4 * 8;
            *(uint2*)(sm + SM_AHI + off) = hi;
            *(uint2*)(sm + SM_ALO + off) = lo;
        }
#pragma unroll
        for (int i = 0; i < 4; i++) {
            int p = tid + i * 256;
            int row = p >> 4;
            int c4 = p & 15;
            const float* src = TRANSB ? &B[(long)(bn + row) * ldb + k0 + c4 * 4]
                                      : &B[(long)(k0 + row) * ldb + bn + c4 * 4];
            float4 v = *(const float4*)src;
            uint2 hi, lo;
            split4(v, hi, lo);
            uint32_t off = row * ROWB + c4 * 8;
            *(uint2*)(sm + SM_BHI + off) = hi;
            *(uint2*)(sm + SM_BLO + off) = lo;
        }
        __syncthreads();

#pragma unroll
        for (int ks = 0; ks < 4; ks++) {
            int kk = ks * 16;
            uint32_t bh[4][2], bl[4][2];
#pragma unroll
            for (int g = 0; g < 2; g++) {
                uint32_t r[4];
                if (TRANSB) {
                    uint32_t off = (uint32_t)(wn * 32 + g * 16 + bnr) * ROWB + (kk + bkc) * 2;
                    ldsm4(r, sb + SM_BHI + off);
                    bh[g*2][0]=r[0]; bh[g*2][1]=r[1]; bh[g*2+1][0]=r[2]; bh[g*2+1][1]=r[3];
                    ldsm4(r, sb + SM_BLO + off);
                    bl[g*2][0]=r[0]; bl[g*2][1]=r[1]; bl[g*2+1][0]=r[2]; bl[g*2+1][1]=r[3];
                } else {
                    uint32_t off = (uint32_t)(kk + bkr) * ROWB + (wn * 32 + g * 16 + bnc) * 2;
                    ldsm4t(r, sb + SM_BHI + off);
                    bh[g*2][0]=r[0]; bh[g*2][1]=r[1]; bh[g*2+1][0]=r[2]; bh[g*2+1][1]=r[3];
                    ldsm4t(r, sb + SM_BLO + off);
                    bl[g*2][0]=r[0]; bl[g*2][1]=r[1]; bl[g*2+1][0]=r[2]; bl[g*2+1][1]=r[3];
                }
            }
            uint32_t ah[2][4], al[2][4];
#pragma unroll
            for (int i = 0; i < 2; i++) {
                uint32_t off = (uint32_t)(wm * 32 + i * 16 + am) * ROWB + (kk + ak) * 2;
                ldsm4(ah[i], sb + SM_AHI + off);
                ldsm4(al[i], sb + SM_ALO + off);
            }
#pragma unroll
            for (int i = 0; i < 2; i++)
#pragma unroll
                for (int f = 0; f < 4; f++) {
                    mma16816(acc[i][f], ah[i], bh[f]);
                    mma16816(acc[i][f], ah[i], bl[f]);
                    mma16816(acc[i][f], al[i], bh[f]);
                }
        }
        __syncthreads();
    }

#pragma unroll
    for (int i = 0; i < 2; i++) {
#pragma unroll
        for (int f = 0; f < 4; f++) {
            int row = bm + wm * 32 + i * 16 + (lane >> 2);
            int col = bn + wn * 32 + f * 8 + (lane & 3) * 2;
            float2 bb = make_float2(0.f, 0.f);
            if (HASBIAS) bb = *(const float2*)&bias[(long)z * zBias + col - bn + bn];
            float2 o0, o1;
            o0.x = alpha * acc[i][f][0] + bb.x;
            o0.y = alpha * acc[i][f][1] + bb.y;
            o1.x = alpha * acc[i][f][2] + bb.x;
            o1.y = alpha * acc[i][f][3] + bb.y;
            *(float2*)&C[(long)row * ldc + col] = o0;
            *(float2*)&C[(long)(row + 8) * ldc + col] = o1;
        }
    }
}

// ---------------- bias folding: bq_eff, bv_eff, bo_eff -----------------
__global__ void bias_fold(const float* __restrict__ ipw, const float* __restrict__ ipb,
                          const float* __restrict__ bq,  const float* __restrict__ bv,
                          const float* __restrict__ out_w, const float* __restrict__ mob,
                          const float* __restrict__ out_b)
{
    int gw = (blockIdx.x * blockDim.x + threadIdx.x) >> 5;
    int lane = threadIdx.x & 31;
    if (gw >= 3 * Ee) return;
    int which = gw / Ee, i = gw % Ee;
    const float* rowp;
    const float* vec;
    float add;
    if (which == 0)      { rowp = ipw + (long)i * Ee;            vec = bq;  add = ipb[i]; }
    else if (which == 1) { rowp = ipw + (long)(2 * Ee + i) * Ee; vec = bv;  add = ipb[2 * Ee + i]; }
    else                 { rowp = out_w + (long)i * Ee;          vec = mob; add = out_b[i]; }
    float s = 0.f;
    for (int k = lane; k < Ee; k += 32) s += rowp[k] * vec[k];
#pragma unroll
    for (int o = 16; o; o >>= 1) s += __shfl_xor_sync(0xffffffffu, s, o);
    if (lane == 0) g_beff[gw] = s + add;
}

// ---------------- segment starts (batch sorted, all B present) -----------------
__global__ void segstart_kernel(const int* __restrict__ batch)
{
    int n = blockIdx.x * 256 + threadIdx.x;
    if (n < Nn) {
        int b = batch[n];
        if (n == 0 || batch[n - 1] != b) g_segstart[b] = n;
    }
    if (n == 0) g_segstart[Bb] = Nn;
}

// ================= fused segment attention =================
// One block per graph b. Online softmax over 32-node chunks:
//   phase A: logits for the chunk (4 nodes/warp, qhat from SMEM)
//   stats:   per-head running max/Z update + p = exp(l - m)
//   phase C: acc[h][col] += p[n,h] * X[n,col]  (X rows hot in L1/L2 from phase A)
// Final: g_xw[b,h,:] = acc[h,:] / Z[h]
__global__ void __launch_bounds__(256) fused_attn_kernel(const float* __restrict__ X)
{
    __shared__ float qsh[4096];        // qhat[b]  [8][512]
    __shared__ float lgsh[32][9];      // chunk logits (padded: conflict-free col reads)
    __shared__ float psh[32][8];       // chunk p values (16B-aligned rows)
    __shared__ float st_m[8], st_Z[8], st_f[8];

    int b = blockIdx.x;
    int t = threadIdx.x;
    int w = t >> 5, lane = t & 31;
    int s0 = g_segstart[b], e0 = g_segstart[b + 1];

    {
        const float4* src = (const float4*)(g_qhat + (size_t)b * (Hh * Ee));
        float4* dst = (float4*)qsh;
#pragma unroll
        for (int i = 0; i < 4; i++) dst[t + 256 * i] = src[t + 256 * i];
    }
    if (t < 8) { st_m[t] = -1e30f; st_Z[t] = 0.f; }
    __syncthreads();

    float acc[8][2];
#pragma unroll
    for (int h = 0; h < 8; h++) { acc[h][0] = 0.f; acc[h][1] = 0.f; }

    for (int base = s0; base < e0; base += 32) {
        int cnt = min(32, e0 - base);

        // ---- phase A: logits, 4 nodes per warp ----
        {
            int nb = base + 4 * w;
            float4 xv[4][4];
#pragma unroll
            for (int j = 0; j < 4; j++) {
                int n = nb + j;
                if (n < e0) {
                    const float4* xr = (const float4*)(X + (size_t)n * Ee);
#pragma unroll
                    for (int i = 0; i < 4; i++) xv[j][i] = xr[lane + 32 * i];
                } else {
#pragma unroll
                    for (int i = 0; i < 4; i++) xv[j][i] = make_float4(0.f, 0.f, 0.f, 0.f);
                }
            }
#pragma unroll
            for (int h = 0; h < 8; h++) {
                const float4* q = (const float4*)qsh + h * 128;
                float4 q0 = q[lane], q1 = q[lane + 32], q2 = q[lane + 64], q3 = q[lane + 96];
                float s[4];
#pragma unroll
                for (int j = 0; j < 4; j++) {
                    float v;
                    v  = xv[j][0].x * q0.x + xv[j][0].y * q0.y + xv[j][0].z * q0.z + xv[j][0].w * q0.w;
                    v += xv[j][1].x * q1.x + xv[j][1].y * q1.y + xv[j][1].z * q1.z + xv[j][1].w * q1.w;
                    v += xv[j][2].x * q2.x + xv[j][2].y * q2.y + xv[j][2].z * q2.z + xv[j][2].w * q2.w;
                    v += xv[j][3].x * q3.x + xv[j][3].y * q3.y + xv[j][3].z * q3.z + xv[j][3].w * q3.w;
                    s[j] = v;
                }
#pragma unroll
                for (int o = 16; o; o >>= 1) {
#pragma unroll
                    for (int j = 0; j < 4; j++) s[j] += __shfl_xor_sync(0xffffffffu, s[j], o);
                }
                if (lane == 0) {
#pragma unroll
                    for (int j = 0; j < 4; j++)
                        lgsh[4 * w + j][h] = (nb + j < e0) ? s[j] : -1e30f;
                }
            }
        }
        __syncthreads();

        // ---- stats: warp w handles head w ----
        if (w < 8) {
            float v = (lane < cnt) ? lgsh[lane][w] : -1e30f;
            float mx = v;
#pragma unroll
            for (int o = 16; o; o >>= 1) mx = fmaxf(mx, __shfl_xor_sync(0xffffffffu, mx, o));
            float mo = st_m[w];
            float mn = fmaxf(mo, mx);
            float p = (lane < cnt) ? __expf(v - mn) : 0.f;
            psh[lane][w] = p;
            float ssum = p;
#pragma unroll
            for (int o = 16; o; o >>= 1) ssum += __shfl_xor_sync(0xffffffffu, ssum, o);
            if (lane == 0) {
                float f = __expf(mo - mn);
                st_f[w] = f;
                st_m[w] = mn;
                st_Z[w] = st_Z[w] * f + ssum;
            }
        }
        __syncthreads();

        // ---- rescale + phase C ----
#pragma unroll
        for (int h = 0; h < 8; h++) {
            float f = st_f[h];
            acc[h][0] *= f;
            acc[h][1] *= f;
        }
        int i = 0;
        for (; i + 4 <= cnt; i += 4) {
            float2 x0 = *(const float2*)&X[(size_t)(base + i + 0) * Ee + 2 * t];
            float2 x1 = *(const float2*)&X[(size_t)(base + i + 1) * Ee + 2 * t];
            float2 x2 = *(const float2*)&X[(size_t)(base + i + 2) * Ee + 2 * t];
            float2 x3 = *(const float2*)&X[(size_t)(base + i + 3) * Ee + 2 * t];
#pragma unroll
            for (int j = 0; j < 4; j++) {
                float2 x = (j == 0) ? x0 : (j == 1) ? x1 : (j == 2) ? x2 : x3;
                float4 p0 = *(const float4*)&psh[i + j][0];
                float4 p1 = *(const float4*)&psh[i + j][4];
                float pw[8] = {p0.x, p0.y, p0.z, p0.w, p1.x, p1.y, p1.z, p1.w};
#pragma unroll
                for (int h = 0; h < 8; h++) {
                    acc[h][0] += pw[h] * x.x;
                    acc[h][1] += pw[h] * x.y;
                }
            }
        }
        for (; i < cnt; i++) {
            float2 x = *(const float2*)&X[(size_t)(base + i) * Ee + 2 * t];
            float4 p0 = *(const float4*)&psh[i][0];
            float4 p1 = *(const float4*)&psh[i][4];
            float pw[8] = {p0.x, p0.y, p0.z, p0.w, p1.x, p1.y, p1.z, p1.w};
#pragma unroll
            for (int h = 0; h < 8; h++) {
                acc[h][0] += pw[h] * x.x;
                acc[h][1] += pw[h] * x.y;
            }
        }
        __syncthreads();
    }

    float rZ[8];
#pragma unroll
    for (int h = 0; h < 8; h++) rZ[h] = 1.f / st_Z[h];
#pragma unroll
    for (int h = 0; h < 8; h++) {
        float2 o = make_float2(acc[h][0] * rZ[h], acc[h][1] * rZ[h]);
        *(float2*)&g_xw[((size_t)b * Hh + h) * Ee + 2 * t] = o;
    }
}

// ---------------- LayerNorm over rows of outbuf -> d_out -----------------
__global__ void __launch_bounds__(256) ln_kernel(const float* __restrict__ lng,
                                                 const float* __restrict__ lnb,
                                                 float* __restrict__ out)
{
    int b = blockIdx.x;
    int t = threadIdx.x;
    float v0 = g_outbuf[(long)b * Ee + t];
    float v1 = g_outbuf[(long)b * Ee + t + 256];
    float s = v0 + v1;
    float q = v0 * v0 + v1 * v1;
#pragma unroll
    for (int o = 16; o; o >>= 1) {
        s += __shfl_xor_sync(0xffffffffu, s, o);
        q += __shfl_xor_sync(0xffffffffu, q, o);
    }
    __shared__ float ss[8], qs[8];
    __shared__ float mu_s, r_s;
    int wid = t >> 5, lane = t & 31;
    if (lane == 0) { ss[wid] = s; qs[wid] = q; }
    __syncthreads();
    if (t == 0) {
        float S = 0.f, Q = 0.f;
#pragma unroll
        for (int i = 0; i < 8; i++) { S += ss[i]; Q += qs[i]; }
        float mu = S / (float)Ee;
        float var = Q / (float)Ee - mu * mu;
        mu_s = mu;
        r_s = 1.f / sqrtf(var + 1e-5f);
    }
    __syncthreads();
    float mu = mu_s, r = r_s;
    out[(long)b * Ee + t]       = (v0 - mu) * r * lng[t]       + lnb[t];
    out[(long)b * Ee + t + 256] = (v1 - mu) * r * lng[t + 256] + lnb[t + 256];
}

// ---------------- launch -----------------
extern "C" void kernel_launch(void* const* d_in, const int* in_sizes, int n_in,
                              void* d_out, int out_size)
{
    (void)in_sizes; (void)n_in; (void)out_size;
    const float* X        = (const float*)d_in[0];   // node_features [N,E]
    const float* scaffold = (const float*)d_in[1];   // [B,E]
    const float* Wq       = (const float*)d_in[2];
    const float* bq       = (const float*)d_in[3];
    const float* Wk       = (const float*)d_in[4];
    const float* Wv       = (const float*)d_in[6];
    const float* bv       = (const float*)d_in[7];
    const float* ipw      = (const float*)d_in[8];   // in_proj_w [3E,E]
    const float* ipb      = (const float*)d_in[9];
    const float* mow      = (const float*)d_in[10];  // mha_out_w
    const float* mob      = (const float*)d_in[11];
    const float* ow       = (const float*)d_in[12];  // out_w
    const float* ob       = (const float*)d_in[13];
    const float* lng      = (const float*)d_in[14];
    const float* lnb      = (const float*)d_in[15];
    const int*   batch    = (const int*)d_in[16];

    void* p;
    cudaGetSymbolAddress(&p, g_Acat);   float* Acat   = (float*)p;
    cudaGetSymbolAddress(&p, g_Bcat);   float* Bcat   = (float*)p;
    cudaGetSymbolAddress(&p, g_Weff);   float* Weff   = (float*)p;
    cudaGetSymbolAddress(&p, g_beff);   float* beff   = (float*)p;
    cudaGetSymbolAddress(&p, g_qq);     float* qq     = (float*)p;
    cudaGetSymbolAddress(&p, g_qhat);   float* qhat   = (float*)p;
    cudaGetSymbolAddress(&p, g_xw);     float* xw     = (float*)p;
    cudaGetSymbolAddress(&p, g_pooled); float* pooled = (float*)p;
    cudaGetSymbolAddress(&p, g_outbuf); float* outbuf = (float*)p;

    cudaFuncSetAttribute(tcgemm<false, false>,
                         cudaFuncAttributeMaxDynamicSharedMemorySize, SM_TOTAL);
    cudaFuncSetAttribute(tcgemm<true, true>,
                         cudaFuncAttributeMaxDynamicSharedMemorySize, SM_TOTAL);

    // concat fold operands: Acat=[Wiq;Wik;Wiv;out_w], Bcat=[Wq;Wk;Wv;mha_out_w]
    cudaMemcpyAsync(Acat,          ipw, (size_t)3 * EE * sizeof(float), cudaMemcpyDeviceToDevice, 0);
    cudaMemcpyAsync(Acat + 3 * EE, ow,  (size_t)EE * sizeof(float),     cudaMemcpyDeviceToDevice, 0);
    cudaMemcpyAsync(Bcat,          Wq,  (size_t)EE * sizeof(float),     cudaMemcpyDeviceToDevice, 0);
    cudaMemcpyAsync(Bcat + EE,     Wk,  (size_t)EE * sizeof(float),     cudaMemcpyDeviceToDevice, 0);
    cudaMemcpyAsync(Bcat + 2 * EE, Wv,  (size_t)EE * sizeof(float),     cudaMemcpyDeviceToDevice, 0);
    cudaMemcpyAsync(Bcat + 3 * EE, mow, (size_t)EE * sizeof(float),     cudaMemcpyDeviceToDevice, 0);

    // fold: Weff[z] = Acat[z] @ Bcat[z]  (z = q,k,v,o), 512x512x512 each (NN)
    tcgemm<false, false><<<dim3(8, 4, 4), 256, SM_TOTAL>>>(Acat, Bcat, Weff, nullptr,
        512, 512, 512, 512, (long)EE, (long)EE, (long)EE, 0, 1.f);

    bias_fold<<<192, 256>>>(ipw, ipb, bq, bv, ow, mob, ob);

    // qq = scaffold @ Wq_eff^T + bq_eff   [4096,512,512] NT
    tcgemm<true, true><<<dim3(8, 32, 1), 256, SM_TOTAL>>>(scaffold, Weff, qq, beff,
        512, Ee, Ee, Ee, 0, 0, 0, 0, 1.f);

    // qhat[b,h,:] = scale * qq[b,h,:] @ Wk_eff_h    [4096,512,64] NN x 8 heads
    tcgemm<false, false><<<dim3(8, 32, 8), 256, SM_TOTAL>>>(qq, Weff + EE, qhat, nullptr,
        Dd, Ee, Ee, Hh * Ee, (long)Dd, (long)Dd * Ee, (long)Ee, 0, 0.125f);

    segstart_kernel<<<Nn / 256, 256>>>(batch);

    // fused logits + online softmax + weighted sum
    fused_attn_kernel<<<Bb, 256>>>(X);

    // pooled[b, h*D+:] = xw[b,h,:] @ Wv_eff_h^T + bv_eff   [4096,64,512] NT x 8 heads
    tcgemm<true, true><<<dim3(1, 32, 8), 256, SM_TOTAL>>>(xw, Weff + 2 * EE, pooled, beff + Ee,
        512, Hh * Ee, Ee, Ee, (long)Ee, (long)Dd * Ee, (long)Dd, Dd, 1.f);

    // out = pooled @ Wo_eff^T + bo_eff   [4096,512,512] NT
    tcgemm<true, true><<<dim3(8, 32, 1), 256, SM_TOTAL>>>(pooled, Weff + 3 * EE, outbuf, beff + 2 * Ee,
        512, Ee, Ee, Ee, 0, 0, 0, 0, 1.f);

    ln_kernel<<<Bb, 256>>>(lng, lnb, (float*)d_out);
}